// round 16
// baseline (speedup 1.0000x reference)
#include <cuda_runtime.h>
#include <cstdint>

#define N_PRE    50000
#define VEC_DIM  300        // 75 float4
#define HIDDEN   128        // 32 float4
#define IN_SIZE  50000
#define OUT_DIM  428        // 107 float4
#define N_TOKENS (64 * 200)

// Cache-policy register: L2 evict_last for the persistent read set (W, vectors).
static __device__ __forceinline__ uint64_t mk_policy_evict_last() {
    uint64_t pol;
    asm volatile("createpolicy.fractional.L2::evict_last.b64 %0, 1.0;"
                 : "=l"(pol));
    return pol;
}
static __device__ __forceinline__ float ldg_el_f32(const float* p, uint64_t pol) {
    float v;
    asm volatile("ld.global.nc.L2::cache_hint.f32 %0, [%1], %2;"
                 : "=f"(v) : "l"(p), "l"(pol));
    return v;
}
static __device__ __forceinline__ float4 ldg_el_f128(const float4* p, uint64_t pol) {
    float4 v;
    asm volatile("ld.global.nc.L2::cache_hint.v4.f32 {%0,%1,%2,%3}, [%4], %5;"
                 : "=f"(v.x), "=f"(v.y), "=f"(v.z), "=f"(v.w)
                 : "l"(p), "l"(pol));
    return v;
}
static __device__ __forceinline__ void stg_cs_f128(float4* p, float4 v) {
    asm volatile("st.global.cs.v4.f32 [%0], {%1,%2,%3,%4};"
                 :: "l"(p), "f"(v.x), "f"(v.y), "f"(v.z), "f"(v.w) : "memory");
}

// Champion (R11): one 128-thread block per token.
//  pre : 75 float4 vector copy (evict_last) + 32 float4 bias, .cs stores
//  oov : 75 zero stores + warp0 gather: 4 independent diverged evict_last
//        W loads per lane (MLP=4) fused with bias -> one float4 .cs store.
// All reads of the fixed cross-replay set (W sectors, vector rows) carry an
// L2 evict_last policy; the 22MB/replay output stream is evict-early (.cs).
__global__ __launch_bounds__(128) void encoder_kernel(
    const int*    __restrict__ tokens,    // [N_TOKENS]
    const float4* __restrict__ vectors4,  // [N_PRE * 75]
    const float*  __restrict__ W,         // [HIDDEN, IN_SIZE]
    const float4* __restrict__ b4,        // [32]
    float4*       __restrict__ out4)      // [N_TOKENS * 107]
{
    const int t   = blockIdx.x;
    const int tid = threadIdx.x;
    const int tok = __ldg(&tokens[t]);        // tiny, broadcast

    float4* orow = out4 + (size_t)t * (OUT_DIM / 4);

    if (tok < N_PRE) {
        const uint64_t pol = mk_policy_evict_last();
        const float4* vrow = vectors4 + (size_t)tok * (VEC_DIM / 4);
        if (tid < 75) {
            float4 v = ldg_el_f128(&vrow[tid], pol);
            stg_cs_f128(&orow[tid], v);
        }
        if (tid < 32) {
            stg_cs_f128(&orow[75 + tid], __ldg(&b4[tid]));
        }
    } else {
        const float4 z = make_float4(0.f, 0.f, 0.f, 0.f);
        if (tid < 75) stg_cs_f128(&orow[tid], z);
        if (tid < 32) {
            const uint64_t pol = mk_policy_evict_last();
            const int c = tok - N_PRE;
            const float* Wc = W + c + (size_t)(4 * tid) * IN_SIZE;
            // 4 independent pinned gathers (MLP=4), then one vectorized store
            float w0 = ldg_el_f32(Wc, pol);
            float w1 = ldg_el_f32(Wc + (size_t)IN_SIZE, pol);
            float w2 = ldg_el_f32(Wc + (size_t)2 * IN_SIZE, pol);
            float w3 = ldg_el_f32(Wc + (size_t)3 * IN_SIZE, pol);
            float4 bb = __ldg(&b4[tid]);
            float4 h = make_float4(bb.x + w0, bb.y + w1, bb.z + w2, bb.w + w3);
            stg_cs_f128(&orow[75 + tid], h);
        }
    }
}

extern "C" void kernel_launch(void* const* d_in, const int* in_sizes, int n_in,
                              void* d_out, int out_size)
{
    // metadata order: tokens (int32), vectors (f32), W (f32), b (f32)
    const int*    tokens  = (const int*)   d_in[0];
    const float4* vectors = (const float4*)d_in[1];
    const float*  W       = (const float*) d_in[2];
    const float4* b       = (const float4*)d_in[3];
    float4*       out     = (float4*)      d_out;

    encoder_kernel<<<N_TOKENS, 128>>>(tokens, vectors, W, b, out);
}

// round 17
// speedup vs baseline: 1.0547x; 1.0547x over previous
#include <cuda_runtime.h>
#include <cstdint>

#define N_PRE    50000
#define VEC_DIM  300        // 75 float4
#define HIDDEN   128        // 32 float4
#define IN_SIZE  50000
#define OUT_DIM  428        // 107 float4
#define N_TOKENS (64 * 200)
#define TOK_PER_BLOCK 2     // two independent 128-thread halves per block

// Cache-policy register: L2 evict_last for the persistent read set (W, vectors).
static __device__ __forceinline__ uint64_t mk_policy_evict_last() {
    uint64_t pol;
    asm volatile("createpolicy.fractional.L2::evict_last.b64 %0, 1.0;"
                 : "=l"(pol));
    return pol;
}
static __device__ __forceinline__ float ldg_el_f32(const float* p, uint64_t pol) {
    float v;
    asm volatile("ld.global.nc.L2::cache_hint.f32 %0, [%1], %2;"
                 : "=f"(v) : "l"(p), "l"(pol));
    return v;
}
static __device__ __forceinline__ float4 ldg_el_f128(const float4* p, uint64_t pol) {
    float4 v;
    asm volatile("ld.global.nc.L2::cache_hint.v4.f32 {%0,%1,%2,%3}, [%4], %5;"
                 : "=f"(v.x), "=f"(v.y), "=f"(v.z), "=f"(v.w)
                 : "l"(p), "l"(pol));
    return v;
}
static __device__ __forceinline__ void stg_cs_f128(float4* p, float4 v) {
    asm volatile("st.global.cs.v4.f32 [%0], {%1,%2,%3,%4};"
                 :: "l"(p), "f"(v.x), "f"(v.y), "f"(v.z), "f"(v.w) : "memory");
}

// Champion body (R11), 2 tokens per 256-thread block:
//  pre : 75 float4 vector copy (evict_last) + 32 float4 bias, .cs stores
//  oov : 75 zero stores + gather half-warp group: 4 independent diverged
//        evict_last W loads per lane (MLP=4) fused with bias -> float4 .cs.
__global__ __launch_bounds__(256) void encoder_kernel(
    const int*    __restrict__ tokens,    // [N_TOKENS]
    const float4* __restrict__ vectors4,  // [N_PRE * 75]
    const float*  __restrict__ W,         // [HIDDEN, IN_SIZE]
    const float4* __restrict__ b4,        // [32]
    float4*       __restrict__ out4)      // [N_TOKENS * 107]
{
    const int half = threadIdx.x >> 7;            // 0 or 1: which token
    const int tid  = threadIdx.x & 127;           // id within the 128-thr group
    const int t    = blockIdx.x * TOK_PER_BLOCK + half;
    const int tok  = __ldg(&tokens[t]);           // broadcast per half

    float4* orow = out4 + (size_t)t * (OUT_DIM / 4);

    if (tok < N_PRE) {
        const uint64_t pol = mk_policy_evict_last();
        const float4* vrow = vectors4 + (size_t)tok * (VEC_DIM / 4);
        if (tid < 75) {
            float4 v = ldg_el_f128(&vrow[tid], pol);
            stg_cs_f128(&orow[tid], v);
        }
        if (tid < 32) {
            stg_cs_f128(&orow[75 + tid], __ldg(&b4[tid]));
        }
    } else {
        const float4 z = make_float4(0.f, 0.f, 0.f, 0.f);
        if (tid < 75) stg_cs_f128(&orow[tid], z);
        if (tid < 32) {
            const uint64_t pol = mk_policy_evict_last();
            const int c = tok - N_PRE;
            const float* Wc = W + c + (size_t)(4 * tid) * IN_SIZE;
            // 4 independent pinned gathers (MLP=4), then one vectorized store
            float w0 = ldg_el_f32(Wc, pol);
            float w1 = ldg_el_f32(Wc + (size_t)IN_SIZE, pol);
            float w2 = ldg_el_f32(Wc + (size_t)2 * IN_SIZE, pol);
            float w3 = ldg_el_f32(Wc + (size_t)3 * IN_SIZE, pol);
            float4 bb = __ldg(&b4[tid]);
            float4 h = make_float4(bb.x + w0, bb.y + w1, bb.z + w2, bb.w + w3);
            stg_cs_f128(&orow[75 + tid], h);
        }
    }
}

extern "C" void kernel_launch(void* const* d_in, const int* in_sizes, int n_in,
                              void* d_out, int out_size)
{
    // metadata order: tokens (int32), vectors (f32), W (f32), b (f32)
    const int*    tokens  = (const int*)   d_in[0];
    const float4* vectors = (const float4*)d_in[1];
    const float*  W       = (const float*) d_in[2];
    const float4* b       = (const float4*)d_in[3];
    float4*       out     = (float4*)      d_out;

    encoder_kernel<<<N_TOKENS / TOK_PER_BLOCK, 256>>>(tokens, vectors, W, b, out);
}